// round 5
// baseline (speedup 1.0000x reference)
#include <cuda_runtime.h>
#include <cuda_bf16.h>

#define NMAX 50000
#define EMAX 800000

// Persistent scratch (device globals: no allocation allowed in kernel_launch)
__device__ float g_hs[NMAX * 128];    // scaled hidden: (X@W) * dinv[row]
__device__ float g_out[NMAX * 128];   // layer output after aggregate+bias+relu
__device__ float g_dinv[NMAX];
__device__ int   g_deg[NMAX];
__device__ int   g_cur[NMAX];
__device__ int   g_rowptr[NMAX + 1];
__device__ int   g_esrc[EMAX];

// ---------------- packed f32x2 helpers (Blackwell FFMA2, PTX-only) ----------
__device__ __forceinline__ unsigned long long pack2(float lo, float hi) {
    unsigned long long r;
    asm("mov.b64 %0, {%1, %2};" : "=l"(r) : "f"(lo), "f"(hi));
    return r;
}
__device__ __forceinline__ void unpack2(unsigned long long v, float& lo, float& hi) {
    asm("mov.b64 {%0, %1}, %2;" : "=f"(lo), "=f"(hi) : "l"(v));
}
__device__ __forceinline__ unsigned long long ffma2(unsigned long long a,
                                                    unsigned long long b,
                                                    unsigned long long c) {
    unsigned long long d;
    asm("fma.rn.f32x2 %0, %1, %2, %3;" : "=l"(d) : "l"(a), "l"(b), "l"(c));
    return d;
}

// ---------------- CSR build ----------------
__global__ void k_init(int n) {
    int i = blockIdx.x * blockDim.x + threadIdx.x;
    if (i < n) { g_deg[i] = 0; g_cur[i] = 0; }
}

__global__ void k_hist(const int* __restrict__ ei, int m) {
    int e = blockIdx.x * blockDim.x + threadIdx.x;
    if (e < m) atomicAdd(&g_deg[ei[m + e]], 1);   // second row = dst
}

__global__ void k_dinv(int n) {
    int i = blockIdx.x * blockDim.x + threadIdx.x;
    if (i < n) g_dinv[i] = rsqrtf((float)(g_deg[i] + 1));  // +1 self loop
}

// single-block exclusive scan over g_deg -> g_rowptr (n <= 50176)
__global__ void k_scan(int n) {
    __shared__ int s[1024];
    int tid = threadIdx.x;
    int chunk = (n + 1023) / 1024;
    int start = tid * chunk;
    int end = min(start + chunk, n);
    int sum = 0;
    for (int i = start; i < end; i++) sum += g_deg[i];
    s[tid] = sum;
    __syncthreads();
    for (int off = 1; off < 1024; off <<= 1) {
        int t = (tid >= off) ? s[tid - off] : 0;
        __syncthreads();
        s[tid] += t;
        __syncthreads();
    }
    int run = s[tid] - sum;   // exclusive prefix
    for (int i = start; i < end; i++) { g_rowptr[i] = run; run += g_deg[i]; }
    if (tid == 1023) g_rowptr[n] = s[1023];
}

__global__ void k_fill(const int* __restrict__ ei, int m) {
    int e = blockIdx.x * blockDim.x + threadIdx.x;
    if (e < m) {
        int d = ei[m + e];
        int pos = g_rowptr[d] + atomicAdd(&g_cur[d], 1);
        g_esrc[pos] = ei[e];
    }
}

// ---------------- GEMM: hs = (X @ W) * dinv[row] ----------------
// 64 rows/block, 256 threads. Thread tile: 8 rows x 4 cols via FFMA2 on row pairs.
// X staged transposed in smem (pad 66) so row-pairs load as aligned LDS.64.
__global__ void __launch_bounds__(256, 2)
k_gemm(const float* __restrict__ Xext, const float* __restrict__ W, int n,
       int use_internal) {
    const float* __restrict__ X = use_internal ? (const float*)g_out : Xext;
    __shared__ float Xs[128 * 66];   // Xs[k*66 + r] = X[row0+r][k], r<64
    const int tid = threadIdx.x;
    const int row0 = blockIdx.x * 64;

#pragma unroll
    for (int i = 0; i < 8; i++) {
        int idx = i * 256 + tid;
        int r = idx >> 5;          // 0..63
        int q = idx & 31;          // k quad
        float4 v = make_float4(0.f, 0.f, 0.f, 0.f);
        int gr = row0 + r;
        if (gr < n) v = *reinterpret_cast<const float4*>(X + (size_t)gr * 128 + q * 4);
        Xs[(4 * q + 0) * 66 + r] = v.x;
        Xs[(4 * q + 1) * 66 + r] = v.y;
        Xs[(4 * q + 2) * 66 + r] = v.z;
        Xs[(4 * q + 3) * 66 + r] = v.w;
    }
    __syncthreads();

    const int cg = tid & 31;   // col group: cols cg*4..cg*4+3
    const int rg = tid >> 5;   // row group: rows rg*8..rg*8+7
    unsigned long long acc[4][4];   // [row pair p][col c] = {row 2p, row 2p+1}
#pragma unroll
    for (int p = 0; p < 4; p++)
#pragma unroll
        for (int c = 0; c < 4; c++) acc[p][c] = 0ull;

    const float* wp = W + cg * 4;
    const float* xb = &Xs[rg * 8];
#pragma unroll 4
    for (int k = 0; k < 128; k++) {
        float4 w4 = *reinterpret_cast<const float4*>(wp + k * 128);
        unsigned long long ws0 = pack2(w4.x, w4.x);
        unsigned long long ws1 = pack2(w4.y, w4.y);
        unsigned long long ws2 = pack2(w4.z, w4.z);
        unsigned long long ws3 = pack2(w4.w, w4.w);
        const unsigned long long* xk =
            reinterpret_cast<const unsigned long long*>(xb + k * 66);
        unsigned long long xp0 = xk[0], xp1 = xk[1], xp2 = xk[2], xp3 = xk[3];
        acc[0][0] = ffma2(xp0, ws0, acc[0][0]);
        acc[0][1] = ffma2(xp0, ws1, acc[0][1]);
        acc[0][2] = ffma2(xp0, ws2, acc[0][2]);
        acc[0][3] = ffma2(xp0, ws3, acc[0][3]);
        acc[1][0] = ffma2(xp1, ws0, acc[1][0]);
        acc[1][1] = ffma2(xp1, ws1, acc[1][1]);
        acc[1][2] = ffma2(xp1, ws2, acc[1][2]);
        acc[1][3] = ffma2(xp1, ws3, acc[1][3]);
        acc[2][0] = ffma2(xp2, ws0, acc[2][0]);
        acc[2][1] = ffma2(xp2, ws1, acc[2][1]);
        acc[2][2] = ffma2(xp2, ws2, acc[2][2]);
        acc[2][3] = ffma2(xp2, ws3, acc[2][3]);
        acc[3][0] = ffma2(xp3, ws0, acc[3][0]);
        acc[3][1] = ffma2(xp3, ws1, acc[3][1]);
        acc[3][2] = ffma2(xp3, ws2, acc[3][2]);
        acc[3][3] = ffma2(xp3, ws3, acc[3][3]);
    }

#pragma unroll
    for (int p = 0; p < 4; p++) {
        float lo0, hi0, lo1, hi1, lo2, hi2, lo3, hi3;
        unpack2(acc[p][0], lo0, hi0);
        unpack2(acc[p][1], lo1, hi1);
        unpack2(acc[p][2], lo2, hi2);
        unpack2(acc[p][3], lo3, hi3);
        int r = row0 + rg * 8 + 2 * p;
        if (r < n) {
            float s = g_dinv[r];
            float4 o = make_float4(lo0 * s, lo1 * s, lo2 * s, lo3 * s);
            *reinterpret_cast<float4*>(&g_hs[(size_t)r * 128 + cg * 4]) = o;
        }
        if (r + 1 < n) {
            float s = g_dinv[r + 1];
            float4 o = make_float4(hi0 * s, hi1 * s, hi2 * s, hi3 * s);
            *reinterpret_cast<float4*>(&g_hs[(size_t)(r + 1) * 128 + cg * 4]) = o;
        }
    }
}

// ---------------- aggregate: out[d] = relu(dinv[d]*(sum_in hs[s] + hs[d]) + b)
// one warp per node, each lane owns 4 contiguous columns (float4).
// rowptr/dinv loaded once per warp (lane 0) and shuffled; 8-deep gather MLP.
__global__ void __launch_bounds__(256)
k_agg(const float* __restrict__ bias, int n) {
    const float* __restrict__ hs = g_hs;
    const int* __restrict__ esrc = g_esrc;
    int w = (blockIdx.x * blockDim.x + threadIdx.x) >> 5;
    int lane = threadIdx.x & 31;
    if (w >= n) return;

    int e0 = 0, e1 = 0;
    float sc = 0.f;
    if (lane == 0) {
        e0 = g_rowptr[w];
        e1 = g_rowptr[w + 1];
        sc = g_dinv[w];
    }
    e0 = __shfl_sync(0xffffffffu, e0, 0);
    e1 = __shfl_sync(0xffffffffu, e1, 0);
    sc = __shfl_sync(0xffffffffu, sc, 0);

    size_t coff = (size_t)lane * 4;
    float4 acc = *reinterpret_cast<const float4*>(hs + (size_t)w * 128 + coff); // self
    float4 acc2 = make_float4(0.f, 0.f, 0.f, 0.f);
    int e = e0;
    for (; e + 8 <= e1; e += 8) {
        int s0 = __ldg(esrc + e),     s1 = __ldg(esrc + e + 1);
        int s2 = __ldg(esrc + e + 2), s3 = __ldg(esrc + e + 3);
        int s4 = __ldg(esrc + e + 4), s5 = __ldg(esrc + e + 5);
        int s6 = __ldg(esrc + e + 6), s7 = __ldg(esrc + e + 7);
        float4 v0 = *reinterpret_cast<const float4*>(hs + (size_t)s0 * 128 + coff);
        float4 v1 = *reinterpret_cast<const float4*>(hs + (size_t)s1 * 128 + coff);
        float4 v2 = *reinterpret_cast<const float4*>(hs + (size_t)s2 * 128 + coff);
        float4 v3 = *reinterpret_cast<const float4*>(hs + (size_t)s3 * 128 + coff);
        float4 v4 = *reinterpret_cast<const float4*>(hs + (size_t)s4 * 128 + coff);
        float4 v5 = *reinterpret_cast<const float4*>(hs + (size_t)s5 * 128 + coff);
        float4 v6 = *reinterpret_cast<const float4*>(hs + (size_t)s6 * 128 + coff);
        float4 v7 = *reinterpret_cast<const float4*>(hs + (size_t)s7 * 128 + coff);
        acc.x  += (v0.x + v1.x) + (v2.x + v3.x);
        acc.y  += (v0.y + v1.y) + (v2.y + v3.y);
        acc.z  += (v0.z + v1.z) + (v2.z + v3.z);
        acc.w  += (v0.w + v1.w) + (v2.w + v3.w);
        acc2.x += (v4.x + v5.x) + (v6.x + v7.x);
        acc2.y += (v4.y + v5.y) + (v6.y + v7.y);
        acc2.z += (v4.z + v5.z) + (v6.z + v7.z);
        acc2.w += (v4.w + v5.w) + (v6.w + v7.w);
    }
    for (; e + 4 <= e1; e += 4) {
        int s0 = __ldg(esrc + e),     s1 = __ldg(esrc + e + 1);
        int s2 = __ldg(esrc + e + 2), s3 = __ldg(esrc + e + 3);
        float4 v0 = *reinterpret_cast<const float4*>(hs + (size_t)s0 * 128 + coff);
        float4 v1 = *reinterpret_cast<const float4*>(hs + (size_t)s1 * 128 + coff);
        float4 v2 = *reinterpret_cast<const float4*>(hs + (size_t)s2 * 128 + coff);
        float4 v3 = *reinterpret_cast<const float4*>(hs + (size_t)s3 * 128 + coff);
        acc.x += (v0.x + v1.x) + (v2.x + v3.x);
        acc.y += (v0.y + v1.y) + (v2.y + v3.y);
        acc.z += (v0.z + v1.z) + (v2.z + v3.z);
        acc.w += (v0.w + v1.w) + (v2.w + v3.w);
    }
    for (; e < e1; e++) {
        int s = __ldg(esrc + e);
        float4 v = *reinterpret_cast<const float4*>(hs + (size_t)s * 128 + coff);
        acc.x += v.x; acc.y += v.y; acc.z += v.z; acc.w += v.w;
    }
    acc.x += acc2.x; acc.y += acc2.y; acc.z += acc2.z; acc.w += acc2.w;

    float4 b4 = *reinterpret_cast<const float4*>(bias + coff);
    float4 o;
    o.x = fmaxf(fmaf(acc.x, sc, b4.x), 0.f);
    o.y = fmaxf(fmaf(acc.y, sc, b4.y), 0.f);
    o.z = fmaxf(fmaf(acc.z, sc, b4.z), 0.f);
    o.w = fmaxf(fmaf(acc.w, sc, b4.w), 0.f);
    *reinterpret_cast<float4*>(g_out + (size_t)w * 128 + coff) = o;
}

// ---------------- regressor head: pred = h[tgt] @ Wr + br  (8192 x 12) ------
// one thread per target row, 12 register accumulators -> each row loaded ONCE
__global__ void __launch_bounds__(256)
k_head(const int* __restrict__ tgt, const float* __restrict__ Wr,
       const float* __restrict__ br, float* __restrict__ out, int ntgt) {
    __shared__ float Ws[128 * 12];
    for (int i = threadIdx.x; i < 128 * 12; i += 256) Ws[i] = Wr[i];
    __syncthreads();
    int row = blockIdx.x * 256 + threadIdx.x;
    if (row >= ntgt) return;
    const float* __restrict__ h = g_out + (size_t)tgt[row] * 128;
    float acc[12];
#pragma unroll
    for (int c = 0; c < 12; c++) acc[c] = br[c];
#pragma unroll 4
    for (int k = 0; k < 128; k += 4) {
        float4 hv = *reinterpret_cast<const float4*>(h + k);
#pragma unroll
        for (int c = 0; c < 12; c++) {
            acc[c] = fmaf(hv.x, Ws[(k + 0) * 12 + c], acc[c]);
            acc[c] = fmaf(hv.y, Ws[(k + 1) * 12 + c], acc[c]);
            acc[c] = fmaf(hv.z, Ws[(k + 2) * 12 + c], acc[c]);
            acc[c] = fmaf(hv.w, Ws[(k + 3) * 12 + c], acc[c]);
        }
    }
#pragma unroll
    for (int c = 0; c < 12; c++) out[row * 12 + c] = acc[c];
}

// ---------------- launch ----------------
extern "C" void kernel_launch(void* const* d_in, const int* in_sizes, int n_in,
                              void* d_out, int out_size) {
    const float* x  = (const float*)d_in[0];
    const int*   ei = (const int*)d_in[1];
    const int*  tgt = (const int*)d_in[2];
    const float* W1 = (const float*)d_in[3];
    const float* b1 = (const float*)d_in[4];
    const float* W2 = (const float*)d_in[5];
    const float* b2 = (const float*)d_in[6];
    const float* W3 = (const float*)d_in[7];
    const float* b3 = (const float*)d_in[8];
    const float* Wr = (const float*)d_in[9];
    const float* br = (const float*)d_in[10];

    int n    = in_sizes[0] / 128;   // 50000
    int m    = in_sizes[1] / 2;     // 800000
    int ntgt = in_sizes[2];         // 8192

    // CSR build (deterministic topology; edge order within a node may permute,
    // which only reorders an fp sum — well under the 1e-3 rel-err gate)
    k_init<<<(n + 255) / 256, 256>>>(n);
    k_hist<<<(m + 255) / 256, 256>>>(ei, m);
    k_dinv<<<(n + 255) / 256, 256>>>(n);
    k_scan<<<1, 1024>>>(n);
    k_fill<<<(m + 255) / 256, 256>>>(ei, m);

    int gblocks = (n + 63) / 64;
    int ablocks = (n + 7) / 8;

    k_gemm<<<gblocks, 256>>>(x, W1, n, 0);
    k_agg<<<ablocks, 256>>>(b1, n);
    k_gemm<<<gblocks, 256>>>(nullptr, W2, n, 1);
    k_agg<<<ablocks, 256>>>(b2, n);
    k_gemm<<<gblocks, 256>>>(nullptr, W3, n, 1);
    k_agg<<<ablocks, 256>>>(b3, n);

    k_head<<<(ntgt * 12 + 255) / 256, 256>>>(tgt, Wr, br, (float*)d_out, ntgt);
}

// round 7
// speedup vs baseline: 1.1698x; 1.1698x over previous
#include <cuda_runtime.h>
#include <cuda_bf16.h>

#define NMAX 50000
#define EMAX 800000

// Persistent scratch (device globals: no allocation allowed in kernel_launch)
__device__ float g_hs[NMAX * 128];    // scaled hidden: (X@W) * dinv[row]
__device__ float g_out[NMAX * 128];   // layer output after aggregate+bias+relu
__device__ float g_dinv[NMAX];
__device__ int   g_deg[NMAX];
__device__ int   g_cur[NMAX];
__device__ int   g_rowptr[NMAX + 1];
__device__ int   g_esrc[EMAX];
__device__ int   g_bsum[256];         // per-block partial sums for scan
__device__ int   g_boff[256];         // exclusive block offsets

// ---------------- packed f32x2 helpers (Blackwell FFMA2, PTX-only) ----------
__device__ __forceinline__ unsigned long long pack2(float lo, float hi) {
    unsigned long long r;
    asm("mov.b64 %0, {%1, %2};" : "=l"(r) : "f"(lo), "f"(hi));
    return r;
}
__device__ __forceinline__ void unpack2(unsigned long long v, float& lo, float& hi) {
    asm("mov.b64 {%0, %1}, %2;" : "=f"(lo), "=f"(hi) : "l"(v));
}
__device__ __forceinline__ unsigned long long ffma2(unsigned long long a,
                                                    unsigned long long b,
                                                    unsigned long long c) {
    unsigned long long d;
    asm("fma.rn.f32x2 %0, %1, %2, %3;" : "=l"(d) : "l"(a), "l"(b), "l"(c));
    return d;
}

// ---------------- CSR build ----------------
__global__ void k_init(int n) {
    int i = blockIdx.x * blockDim.x + threadIdx.x;
    if (i < n) { g_deg[i] = 0; g_cur[i] = 0; }
}

__global__ void k_hist(const int* __restrict__ ei, int m) {
    int e = blockIdx.x * blockDim.x + threadIdx.x;
    if (e < m) atomicAdd(&g_deg[ei[m + e]], 1);   // second row = dst
}

// --- 3-phase full-chip scan (replaces 48us single-block k_scan) ---
// phase 1: per-block reduction of deg tiles; also computes dinv (deg in regs)
__global__ void k_scan1(int n) {
    __shared__ int s[256];
    int i = blockIdx.x * 256 + threadIdx.x;
    int d = (i < n) ? g_deg[i] : 0;
    if (i < n) g_dinv[i] = rsqrtf((float)(d + 1));   // +1 self loop
    s[threadIdx.x] = d;
    __syncthreads();
#pragma unroll
    for (int off = 128; off > 0; off >>= 1) {
        if (threadIdx.x < off) s[threadIdx.x] += s[threadIdx.x + off];
        __syncthreads();
    }
    if (threadIdx.x == 0) g_bsum[blockIdx.x] = s[0];
}

// phase 2: single small block scans <=256 partials -> exclusive block offsets
__global__ void k_scan2(int nblk, int n) {
    __shared__ int s[256];
    int t = threadIdx.x;
    int v = (t < nblk) ? g_bsum[t] : 0;
    s[t] = v;
    __syncthreads();
#pragma unroll
    for (int off = 1; off < 256; off <<= 1) {
        int x = (t >= off) ? s[t - off] : 0;
        __syncthreads();
        s[t] += x;
        __syncthreads();
    }
    g_boff[t] = s[t] - v;              // exclusive offset for block t
    if (t == 255) g_rowptr[n] = s[255];  // grand total
}

// phase 3: intra-block exclusive scan (warp shuffles) + block offset -> rowptr
__global__ void k_scan3(int n) {
    __shared__ int ws[8];
    int i = blockIdx.x * 256 + threadIdx.x;
    int lane = threadIdx.x & 31, wid = threadIdx.x >> 5;
    int v = (i < n) ? g_deg[i] : 0;
    int x = v;
#pragma unroll
    for (int off = 1; off < 32; off <<= 1) {
        int y = __shfl_up_sync(0xffffffffu, x, off);
        if (lane >= off) x += y;
    }
    if (lane == 31) ws[wid] = x;
    __syncthreads();
    if (wid == 0) {
        int w = (lane < 8) ? ws[lane] : 0;
#pragma unroll
        for (int off = 1; off < 8; off <<= 1) {
            int y = __shfl_up_sync(0xffffffffu, w, off);
            if (lane >= off) w += y;
        }
        if (lane < 8) ws[lane] = w;
    }
    __syncthreads();
    int warpoff = (wid > 0) ? ws[wid - 1] : 0;
    if (i < n) g_rowptr[i] = g_boff[blockIdx.x] + warpoff + (x - v);  // exclusive
}

__global__ void k_fill(const int* __restrict__ ei, int m) {
    int e = blockIdx.x * blockDim.x + threadIdx.x;
    if (e < m) {
        int d = ei[m + e];
        int pos = g_rowptr[d] + atomicAdd(&g_cur[d], 1);
        g_esrc[pos] = ei[e];
    }
}

// ---------------- GEMM: hs = (X @ W) * dinv[row] ----------------
// 64 rows/block, 256 threads. Thread tile: 8 rows x 4 cols via FFMA2 on row pairs.
// X staged transposed in smem (pad 66) so row-pairs load as aligned LDS.64.
__global__ void __launch_bounds__(256, 2)
k_gemm(const float* __restrict__ Xext, const float* __restrict__ W, int n,
       int use_internal) {
    const float* __restrict__ X = use_internal ? (const float*)g_out : Xext;
    __shared__ float Xs[128 * 66];   // Xs[k*66 + r] = X[row0+r][k], r<64
    const int tid = threadIdx.x;
    const int row0 = blockIdx.x * 64;

#pragma unroll
    for (int i = 0; i < 8; i++) {
        int idx = i * 256 + tid;
        int r = idx >> 5;          // 0..63
        int q = idx & 31;          // k quad
        float4 v = make_float4(0.f, 0.f, 0.f, 0.f);
        int gr = row0 + r;
        if (gr < n) v = *reinterpret_cast<const float4*>(X + (size_t)gr * 128 + q * 4);
        Xs[(4 * q + 0) * 66 + r] = v.x;
        Xs[(4 * q + 1) * 66 + r] = v.y;
        Xs[(4 * q + 2) * 66 + r] = v.z;
        Xs[(4 * q + 3) * 66 + r] = v.w;
    }
    __syncthreads();

    const int cg = tid & 31;   // col group: cols cg*4..cg*4+3
    const int rg = tid >> 5;   // row group: rows rg*8..rg*8+7
    unsigned long long acc[4][4];   // [row pair p][col c] = {row 2p, row 2p+1}
#pragma unroll
    for (int p = 0; p < 4; p++)
#pragma unroll
        for (int c = 0; c < 4; c++) acc[p][c] = 0ull;

    const float* wp = W + cg * 4;
    const float* xb = &Xs[rg * 8];
#pragma unroll 4
    for (int k = 0; k < 128; k++) {
        float4 w4 = *reinterpret_cast<const float4*>(wp + k * 128);
        unsigned long long ws0 = pack2(w4.x, w4.x);
        unsigned long long ws1 = pack2(w4.y, w4.y);
        unsigned long long ws2 = pack2(w4.z, w4.z);
        unsigned long long ws3 = pack2(w4.w, w4.w);
        const unsigned long long* xk =
            reinterpret_cast<const unsigned long long*>(xb + k * 66);
        unsigned long long xp0 = xk[0], xp1 = xk[1], xp2 = xk[2], xp3 = xk[3];
        acc[0][0] = ffma2(xp0, ws0, acc[0][0]);
        acc[0][1] = ffma2(xp0, ws1, acc[0][1]);
        acc[0][2] = ffma2(xp0, ws2, acc[0][2]);
        acc[0][3] = ffma2(xp0, ws3, acc[0][3]);
        acc[1][0] = ffma2(xp1, ws0, acc[1][0]);
        acc[1][1] = ffma2(xp1, ws1, acc[1][1]);
        acc[1][2] = ffma2(xp1, ws2, acc[1][2]);
        acc[1][3] = ffma2(xp1, ws3, acc[1][3]);
        acc[2][0] = ffma2(xp2, ws0, acc[2][0]);
        acc[2][1] = ffma2(xp2, ws1, acc[2][1]);
        acc[2][2] = ffma2(xp2, ws2, acc[2][2]);
        acc[2][3] = ffma2(xp2, ws3, acc[2][3]);
        acc[3][0] = ffma2(xp3, ws0, acc[3][0]);
        acc[3][1] = ffma2(xp3, ws1, acc[3][1]);
        acc[3][2] = ffma2(xp3, ws2, acc[3][2]);
        acc[3][3] = ffma2(xp3, ws3, acc[3][3]);
    }

#pragma unroll
    for (int p = 0; p < 4; p++) {
        float lo0, hi0, lo1, hi1, lo2, hi2, lo3, hi3;
        unpack2(acc[p][0], lo0, hi0);
        unpack2(acc[p][1], lo1, hi1);
        unpack2(acc[p][2], lo2, hi2);
        unpack2(acc[p][3], lo3, hi3);
        int r = row0 + rg * 8 + 2 * p;
        if (r < n) {
            float s = g_dinv[r];
            float4 o = make_float4(lo0 * s, lo1 * s, lo2 * s, lo3 * s);
            *reinterpret_cast<float4*>(&g_hs[(size_t)r * 128 + cg * 4]) = o;
        }
        if (r + 1 < n) {
            float s = g_dinv[r + 1];
            float4 o = make_float4(hi0 * s, hi1 * s, hi2 * s, hi3 * s);
            *reinterpret_cast<float4*>(&g_hs[(size_t)(r + 1) * 128 + cg * 4]) = o;
        }
    }
}

// ---------------- aggregate: out[d] = relu(dinv[d]*(sum_in hs[s] + hs[d]) + b)
// one warp per node, each lane owns 4 contiguous columns (float4).
// rowptr/dinv loaded once per warp (lane 0) and shuffled; 8-deep gather MLP.
__global__ void __launch_bounds__(256)
k_agg(const float* __restrict__ bias, int n) {
    const float* __restrict__ hs = g_hs;
    const int* __restrict__ esrc = g_esrc;
    int w = (blockIdx.x * blockDim.x + threadIdx.x) >> 5;
    int lane = threadIdx.x & 31;
    if (w >= n) return;

    int e0 = 0, e1 = 0;
    float sc = 0.f;
    if (lane == 0) {
        e0 = g_rowptr[w];
        e1 = g_rowptr[w + 1];
        sc = g_dinv[w];
    }
    e0 = __shfl_sync(0xffffffffu, e0, 0);
    e1 = __shfl_sync(0xffffffffu, e1, 0);
    sc = __shfl_sync(0xffffffffu, sc, 0);

    size_t coff = (size_t)lane * 4;
    float4 acc = *reinterpret_cast<const float4*>(hs + (size_t)w * 128 + coff); // self
    float4 acc2 = make_float4(0.f, 0.f, 0.f, 0.f);
    int e = e0;
    for (; e + 8 <= e1; e += 8) {
        int s0 = __ldg(esrc + e),     s1 = __ldg(esrc + e + 1);
        int s2 = __ldg(esrc + e + 2), s3 = __ldg(esrc + e + 3);
        int s4 = __ldg(esrc + e + 4), s5 = __ldg(esrc + e + 5);
        int s6 = __ldg(esrc + e + 6), s7 = __ldg(esrc + e + 7);
        float4 v0 = *reinterpret_cast<const float4*>(hs + (size_t)s0 * 128 + coff);
        float4 v1 = *reinterpret_cast<const float4*>(hs + (size_t)s1 * 128 + coff);
        float4 v2 = *reinterpret_cast<const float4*>(hs + (size_t)s2 * 128 + coff);
        float4 v3 = *reinterpret_cast<const float4*>(hs + (size_t)s3 * 128 + coff);
        float4 v4 = *reinterpret_cast<const float4*>(hs + (size_t)s4 * 128 + coff);
        float4 v5 = *reinterpret_cast<const float4*>(hs + (size_t)s5 * 128 + coff);
        float4 v6 = *reinterpret_cast<const float4*>(hs + (size_t)s6 * 128 + coff);
        float4 v7 = *reinterpret_cast<const float4*>(hs + (size_t)s7 * 128 + coff);
        acc.x  += (v0.x + v1.x) + (v2.x + v3.x);
        acc.y  += (v0.y + v1.y) + (v2.y + v3.y);
        acc.z  += (v0.z + v1.z) + (v2.z + v3.z);
        acc.w  += (v0.w + v1.w) + (v2.w + v3.w);
        acc2.x += (v4.x + v5.x) + (v6.x + v7.x);
        acc2.y += (v4.y + v5.y) + (v6.y + v7.y);
        acc2.z += (v4.z + v5.z) + (v6.z + v7.z);
        acc2.w += (v4.w + v5.w) + (v6.w + v7.w);
    }
    for (; e + 4 <= e1; e += 4) {
        int s0 = __ldg(esrc + e),     s1 = __ldg(esrc + e + 1);
        int s2 = __ldg(esrc + e + 2), s3 = __ldg(esrc + e + 3);
        float4 v0 = *reinterpret_cast<const float4*>(hs + (size_t)s0 * 128 + coff);
        float4 v1 = *reinterpret_cast<const float4*>(hs + (size_t)s1 * 128 + coff);
        float4 v2 = *reinterpret_cast<const float4*>(hs + (size_t)s2 * 128 + coff);
        float4 v3 = *reinterpret_cast<const float4*>(hs + (size_t)s3 * 128 + coff);
        acc.x += (v0.x + v1.x) + (v2.x + v3.x);
        acc.y += (v0.y + v1.y) + (v2.y + v3.y);
        acc.z += (v0.z + v1.z) + (v2.z + v3.z);
        acc.w += (v0.w + v1.w) + (v2.w + v3.w);
    }
    for (; e < e1; e++) {
        int s = __ldg(esrc + e);
        float4 v = *reinterpret_cast<const float4*>(hs + (size_t)s * 128 + coff);
        acc.x += v.x; acc.y += v.y; acc.z += v.z; acc.w += v.w;
    }
    acc.x += acc2.x; acc.y += acc2.y; acc.z += acc2.z; acc.w += acc2.w;

    float4 b4 = *reinterpret_cast<const float4*>(bias + coff);
    float4 o;
    o.x = fmaxf(fmaf(acc.x, sc, b4.x), 0.f);
    o.y = fmaxf(fmaf(acc.y, sc, b4.y), 0.f);
    o.z = fmaxf(fmaf(acc.z, sc, b4.z), 0.f);
    o.w = fmaxf(fmaf(acc.w, sc, b4.w), 0.f);
    *reinterpret_cast<float4*>(g_out + (size_t)w * 128 + coff) = o;
}

// ---------------- regressor head: pred = h[tgt] @ Wr + br  (8192 x 12) ------
// one thread per target row, 12 register accumulators -> each row loaded ONCE
__global__ void __launch_bounds__(256)
k_head(const int* __restrict__ tgt, const float* __restrict__ Wr,
       const float* __restrict__ br, float* __restrict__ out, int ntgt) {
    __shared__ float Ws[128 * 12];
    for (int i = threadIdx.x; i < 128 * 12; i += 256) Ws[i] = Wr[i];
    __syncthreads();
    int row = blockIdx.x * 256 + threadIdx.x;
    if (row >= ntgt) return;
    const float* __restrict__ h = g_out + (size_t)tgt[row] * 128;
    float acc[12];
#pragma unroll
    for (int c = 0; c < 12; c++) acc[c] = br[c];
#pragma unroll 4
    for (int k = 0; k < 128; k += 4) {
        float4 hv = *reinterpret_cast<const float4*>(h + k);
#pragma unroll
        for (int c = 0; c < 12; c++) {
            acc[c] = fmaf(hv.x, Ws[(k + 0) * 12 + c], acc[c]);
            acc[c] = fmaf(hv.y, Ws[(k + 1) * 12 + c], acc[c]);
            acc[c] = fmaf(hv.z, Ws[(k + 2) * 12 + c], acc[c]);
            acc[c] = fmaf(hv.w, Ws[(k + 3) * 12 + c], acc[c]);
        }
    }
#pragma unroll
    for (int c = 0; c < 12; c++) out[row * 12 + c] = acc[c];
}

// ---------------- launch ----------------
extern "C" void kernel_launch(void* const* d_in, const int* in_sizes, int n_in,
                              void* d_out, int out_size) {
    const float* x  = (const float*)d_in[0];
    const int*   ei = (const int*)d_in[1];
    const int*  tgt = (const int*)d_in[2];
    const float* W1 = (const float*)d_in[3];
    const float* b1 = (const float*)d_in[4];
    const float* W2 = (const float*)d_in[5];
    const float* b2 = (const float*)d_in[6];
    const float* W3 = (const float*)d_in[7];
    const float* b3 = (const float*)d_in[8];
    const float* Wr = (const float*)d_in[9];
    const float* br = (const float*)d_in[10];

    int n    = in_sizes[0] / 128;   // 50000
    int m    = in_sizes[1] / 2;     // 800000
    int ntgt = in_sizes[2];         // 8192

    // CSR build (deterministic topology; edge order within a node may permute,
    // which only reorders an fp sum — well under the 1e-3 rel-err gate)
    int sblocks = (n + 255) / 256;  // 196 <= 256
    k_init<<<sblocks, 256>>>(n);
    k_hist<<<(m + 255) / 256, 256>>>(ei, m);
    k_scan1<<<sblocks, 256>>>(n);   // also computes dinv
    k_scan2<<<1, 256>>>(sblocks, n);
    k_scan3<<<sblocks, 256>>>(n);
    k_fill<<<(m + 255) / 256, 256>>>(ei, m);

    int gblocks = (n + 63) / 64;
    int ablocks = (n + 7) / 8;

    k_gemm<<<gblocks, 256>>>(x, W1, n, 0);
    k_agg<<<ablocks, 256>>>(b1, n);
    k_gemm<<<gblocks, 256>>>(nullptr, W2, n, 1);
    k_agg<<<ablocks, 256>>>(b2, n);
    k_gemm<<<gblocks, 256>>>(nullptr, W3, n, 1);
    k_agg<<<ablocks, 256>>>(b3, n);

    k_head<<<(ntgt * 12 + 255) / 256, 256>>>(tgt, Wr, br, (float*)d_out, ntgt);
}

// round 8
// speedup vs baseline: 1.1761x; 1.0053x over previous
#include <cuda_runtime.h>
#include <cuda_bf16.h>

#define NMAX 50000
#define EMAX 800000

// Persistent scratch (device globals: no allocation allowed in kernel_launch)
__device__ float g_hs[NMAX * 128];    // scaled hidden: (X@W) * dinv[row]
__device__ float g_out[NMAX * 128];   // layer output after aggregate+bias+relu
__device__ float g_dinv[NMAX];
__device__ int   g_deg[NMAX];
__device__ int   g_cur[NMAX];
__device__ int   g_rowptr[NMAX + 1];
__device__ int   g_esrc[EMAX];
__device__ int   g_bsum[256];         // per-block partial sums for scan
__device__ int   g_boff[256];         // exclusive block offsets

// ---------------- packed f32x2 helpers (Blackwell FFMA2, PTX-only) ----------
__device__ __forceinline__ unsigned long long pack2(float lo, float hi) {
    unsigned long long r;
    asm("mov.b64 %0, {%1, %2};" : "=l"(r) : "f"(lo), "f"(hi));
    return r;
}
__device__ __forceinline__ void unpack2(unsigned long long v, float& lo, float& hi) {
    asm("mov.b64 {%0, %1}, %2;" : "=f"(lo), "=f"(hi) : "l"(v));
}
__device__ __forceinline__ unsigned long long ffma2(unsigned long long a,
                                                    unsigned long long b,
                                                    unsigned long long c) {
    unsigned long long d;
    asm("fma.rn.f32x2 %0, %1, %2, %3;" : "=l"(d) : "l"(a), "l"(b), "l"(c));
    return d;
}

// ---------------- CSR build ----------------
__global__ void k_init(int n) {
    int i = blockIdx.x * blockDim.x + threadIdx.x;
    if (i < n) { g_deg[i] = 0; g_cur[i] = 0; }
}

__global__ void k_hist(const int* __restrict__ ei, int m) {
    int e = blockIdx.x * blockDim.x + threadIdx.x;
    if (e < m) atomicAdd(&g_deg[ei[m + e]], 1);   // second row = dst
}

// --- 3-phase full-chip scan ---
// phase 1: per-block reduction of deg tiles; also computes dinv (deg in regs)
__global__ void k_scan1(int n) {
    __shared__ int s[256];
    int i = blockIdx.x * 256 + threadIdx.x;
    int d = (i < n) ? g_deg[i] : 0;
    if (i < n) g_dinv[i] = rsqrtf((float)(d + 1));   // +1 self loop
    s[threadIdx.x] = d;
    __syncthreads();
#pragma unroll
    for (int off = 128; off > 0; off >>= 1) {
        if (threadIdx.x < off) s[threadIdx.x] += s[threadIdx.x + off];
        __syncthreads();
    }
    if (threadIdx.x == 0) g_bsum[blockIdx.x] = s[0];
}

// phase 2: shuffle-based exclusive scan of <=256 partials (2 barriers)
__global__ void k_scan2(int nblk, int n) {
    __shared__ int ws[8];
    int t = threadIdx.x;
    int lane = t & 31, wid = t >> 5;
    int v = (t < nblk) ? g_bsum[t] : 0;
    int x = v;   // inclusive within warp
#pragma unroll
    for (int off = 1; off < 32; off <<= 1) {
        int y = __shfl_up_sync(0xffffffffu, x, off);
        if (lane >= off) x += y;
    }
    if (lane == 31) ws[wid] = x;
    __syncthreads();
    if (wid == 0) {
        int w = (lane < 8) ? ws[lane] : 0;
#pragma unroll
        for (int off = 1; off < 8; off <<= 1) {
            int y = __shfl_up_sync(0xffffffffu, w, off);
            if (lane >= off) w += y;
        }
        if (lane < 8) ws[lane] = w;
    }
    __syncthreads();
    int warpoff = (wid > 0) ? ws[wid - 1] : 0;
    g_boff[t] = warpoff + (x - v);            // exclusive offset for block t
    if (t == 255) g_rowptr[n] = ws[7];        // grand total
}

// phase 3: intra-block exclusive scan (warp shuffles) + block offset -> rowptr
__global__ void k_scan3(int n) {
    __shared__ int ws[8];
    int i = blockIdx.x * 256 + threadIdx.x;
    int lane = threadIdx.x & 31, wid = threadIdx.x >> 5;
    int v = (i < n) ? g_deg[i] : 0;
    int x = v;
#pragma unroll
    for (int off = 1; off < 32; off <<= 1) {
        int y = __shfl_up_sync(0xffffffffu, x, off);
        if (lane >= off) x += y;
    }
    if (lane == 31) ws[wid] = x;
    __syncthreads();
    if (wid == 0) {
        int w = (lane < 8) ? ws[lane] : 0;
#pragma unroll
        for (int off = 1; off < 8; off <<= 1) {
            int y = __shfl_up_sync(0xffffffffu, w, off);
            if (lane >= off) w += y;
        }
        if (lane < 8) ws[lane] = w;
    }
    __syncthreads();
    int warpoff = (wid > 0) ? ws[wid - 1] : 0;
    if (i < n) g_rowptr[i] = g_boff[blockIdx.x] + warpoff + (x - v);  // exclusive
}

__global__ void k_fill(const int* __restrict__ ei, int m) {
    int e = blockIdx.x * blockDim.x + threadIdx.x;
    if (e < m) {
        int d = ei[m + e];
        int pos = g_rowptr[d] + atomicAdd(&g_cur[d], 1);
        g_esrc[pos] = ei[e];
    }
}

// ---------------- GEMM: hs = (X @ W) * dinv[row] ----------------
// 64 rows/block, 256 threads. Thread tile: 8 rows x 4 cols via FFMA2 on row pairs.
// X staged transposed in smem (pad 66) so row-pairs load as aligned LDS.64.
__global__ void __launch_bounds__(256, 2)
k_gemm(const float* __restrict__ Xext, const float* __restrict__ W, int n,
       int use_internal) {
    const float* __restrict__ X = use_internal ? (const float*)g_out : Xext;
    __shared__ float Xs[128 * 66];   // Xs[k*66 + r] = X[row0+r][k], r<64
    const int tid = threadIdx.x;
    const int row0 = blockIdx.x * 64;

#pragma unroll
    for (int i = 0; i < 8; i++) {
        int idx = i * 256 + tid;
        int r = idx >> 5;          // 0..63
        int q = idx & 31;          // k quad
        float4 v = make_float4(0.f, 0.f, 0.f, 0.f);
        int gr = row0 + r;
        if (gr < n) v = *reinterpret_cast<const float4*>(X + (size_t)gr * 128 + q * 4);
        Xs[(4 * q + 0) * 66 + r] = v.x;
        Xs[(4 * q + 1) * 66 + r] = v.y;
        Xs[(4 * q + 2) * 66 + r] = v.z;
        Xs[(4 * q + 3) * 66 + r] = v.w;
    }
    __syncthreads();

    const int cg = tid & 31;   // col group: cols cg*4..cg*4+3
    const int rg = tid >> 5;   // row group: rows rg*8..rg*8+7
    unsigned long long acc[4][4];   // [row pair p][col c] = {row 2p, row 2p+1}
#pragma unroll
    for (int p = 0; p < 4; p++)
#pragma unroll
        for (int c = 0; c < 4; c++) acc[p][c] = 0ull;

    const float* wp = W + cg * 4;
    const float* xb = &Xs[rg * 8];
#pragma unroll 4
    for (int k = 0; k < 128; k++) {
        float4 w4 = *reinterpret_cast<const float4*>(wp + k * 128);
        unsigned long long ws0 = pack2(w4.x, w4.x);
        unsigned long long ws1 = pack2(w4.y, w4.y);
        unsigned long long ws2 = pack2(w4.z, w4.z);
        unsigned long long ws3 = pack2(w4.w, w4.w);
        const unsigned long long* xk =
            reinterpret_cast<const unsigned long long*>(xb + k * 66);
        unsigned long long xp0 = xk[0], xp1 = xk[1], xp2 = xk[2], xp3 = xk[3];
        acc[0][0] = ffma2(xp0, ws0, acc[0][0]);
        acc[0][1] = ffma2(xp0, ws1, acc[0][1]);
        acc[0][2] = ffma2(xp0, ws2, acc[0][2]);
        acc[0][3] = ffma2(xp0, ws3, acc[0][3]);
        acc[1][0] = ffma2(xp1, ws0, acc[1][0]);
        acc[1][1] = ffma2(xp1, ws1, acc[1][1]);
        acc[1][2] = ffma2(xp1, ws2, acc[1][2]);
        acc[1][3] = ffma2(xp1, ws3, acc[1][3]);
        acc[2][0] = ffma2(xp2, ws0, acc[2][0]);
        acc[2][1] = ffma2(xp2, ws1, acc[2][1]);
        acc[2][2] = ffma2(xp2, ws2, acc[2][2]);
        acc[2][3] = ffma2(xp2, ws3, acc[2][3]);
        acc[3][0] = ffma2(xp3, ws0, acc[3][0]);
        acc[3][1] = ffma2(xp3, ws1, acc[3][1]);
        acc[3][2] = ffma2(xp3, ws2, acc[3][2]);
        acc[3][3] = ffma2(xp3, ws3, acc[3][3]);
    }

#pragma unroll
    for (int p = 0; p < 4; p++) {
        float lo0, hi0, lo1, hi1, lo2, hi2, lo3, hi3;
        unpack2(acc[p][0], lo0, hi0);
        unpack2(acc[p][1], lo1, hi1);
        unpack2(acc[p][2], lo2, hi2);
        unpack2(acc[p][3], lo3, hi3);
        int r = row0 + rg * 8 + 2 * p;
        if (r < n) {
            float s = g_dinv[r];
            float4 o = make_float4(lo0 * s, lo1 * s, lo2 * s, lo3 * s);
            *reinterpret_cast<float4*>(&g_hs[(size_t)r * 128 + cg * 4]) = o;
        }
        if (r + 1 < n) {
            float s = g_dinv[r + 1];
            float4 o = make_float4(hi0 * s, hi1 * s, hi2 * s, hi3 * s);
            *reinterpret_cast<float4*>(&g_hs[(size_t)(r + 1) * 128 + cg * 4]) = o;
        }
    }
}

// ---------------- aggregate: out[d] = relu(dinv[d]*(sum_in hs[s] + hs[d]) + b)
// one warp per node, each lane owns 4 contiguous columns (float4).
// rowptr/dinv loaded once per warp (lane 0) and shuffled; 8-deep gather MLP.
__global__ void __launch_bounds__(256)
k_agg(const float* __restrict__ bias, int n) {
    const float* __restrict__ hs = g_hs;
    const int* __restrict__ esrc = g_esrc;
    int w = (blockIdx.x * blockDim.x + threadIdx.x) >> 5;
    int lane = threadIdx.x & 31;
    if (w >= n) return;

    int e0 = 0, e1 = 0;
    float sc = 0.f;
    if (lane == 0) {
        e0 = g_rowptr[w];
        e1 = g_rowptr[w + 1];
        sc = g_dinv[w];
    }
    e0 = __shfl_sync(0xffffffffu, e0, 0);
    e1 = __shfl_sync(0xffffffffu, e1, 0);
    sc = __shfl_sync(0xffffffffu, sc, 0);

    size_t coff = (size_t)lane * 4;
    float4 acc = *reinterpret_cast<const float4*>(hs + (size_t)w * 128 + coff); // self
    float4 acc2 = make_float4(0.f, 0.f, 0.f, 0.f);
    int e = e0;
    for (; e + 8 <= e1; e += 8) {
        int s0 = __ldg(esrc + e),     s1 = __ldg(esrc + e + 1);
        int s2 = __ldg(esrc + e + 2), s3 = __ldg(esrc + e + 3);
        int s4 = __ldg(esrc + e + 4), s5 = __ldg(esrc + e + 5);
        int s6 = __ldg(esrc + e + 6), s7 = __ldg(esrc + e + 7);
        float4 v0 = *reinterpret_cast<const float4*>(hs + (size_t)s0 * 128 + coff);
        float4 v1 = *reinterpret_cast<const float4*>(hs + (size_t)s1 * 128 + coff);
        float4 v2 = *reinterpret_cast<const float4*>(hs + (size_t)s2 * 128 + coff);
        float4 v3 = *reinterpret_cast<const float4*>(hs + (size_t)s3 * 128 + coff);
        float4 v4 = *reinterpret_cast<const float4*>(hs + (size_t)s4 * 128 + coff);
        float4 v5 = *reinterpret_cast<const float4*>(hs + (size_t)s5 * 128 + coff);
        float4 v6 = *reinterpret_cast<const float4*>(hs + (size_t)s6 * 128 + coff);
        float4 v7 = *reinterpret_cast<const float4*>(hs + (size_t)s7 * 128 + coff);
        acc.x  += (v0.x + v1.x) + (v2.x + v3.x);
        acc.y  += (v0.y + v1.y) + (v2.y + v3.y);
        acc.z  += (v0.z + v1.z) + (v2.z + v3.z);
        acc.w  += (v0.w + v1.w) + (v2.w + v3.w);
        acc2.x += (v4.x + v5.x) + (v6.x + v7.x);
        acc2.y += (v4.y + v5.y) + (v6.y + v7.y);
        acc2.z += (v4.z + v5.z) + (v6.z + v7.z);
        acc2.w += (v4.w + v5.w) + (v6.w + v7.w);
    }
    for (; e + 4 <= e1; e += 4) {
        int s0 = __ldg(esrc + e),     s1 = __ldg(esrc + e + 1);
        int s2 = __ldg(esrc + e + 2), s3 = __ldg(esrc + e + 3);
        float4 v0 = *reinterpret_cast<const float4*>(hs + (size_t)s0 * 128 + coff);
        float4 v1 = *reinterpret_cast<const float4*>(hs + (size_t)s1 * 128 + coff);
        float4 v2 = *reinterpret_cast<const float4*>(hs + (size_t)s2 * 128 + coff);
        float4 v3 = *reinterpret_cast<const float4*>(hs + (size_t)s3 * 128 + coff);
        acc.x += (v0.x + v1.x) + (v2.x + v3.x);
        acc.y += (v0.y + v1.y) + (v2.y + v3.y);
        acc.z += (v0.z + v1.z) + (v2.z + v3.z);
        acc.w += (v0.w + v1.w) + (v2.w + v3.w);
    }
    for (; e < e1; e++) {
        int s = __ldg(esrc + e);
        float4 v = *reinterpret_cast<const float4*>(hs + (size_t)s * 128 + coff);
        acc.x += v.x; acc.y += v.y; acc.z += v.z; acc.w += v.w;
    }
    acc.x += acc2.x; acc.y += acc2.y; acc.z += acc2.z; acc.w += acc2.w;

    float4 b4 = *reinterpret_cast<const float4*>(bias + coff);
    float4 o;
    o.x = fmaxf(fmaf(acc.x, sc, b4.x), 0.f);
    o.y = fmaxf(fmaf(acc.y, sc, b4.y), 0.f);
    o.z = fmaxf(fmaf(acc.z, sc, b4.z), 0.f);
    o.w = fmaxf(fmaf(acc.w, sc, b4.w), 0.f);
    *reinterpret_cast<float4*>(g_out + (size_t)w * 128 + coff) = o;
}

// ---------------- regressor head: pred = h[tgt] @ Wr + br  (8192 x 12) ------
// one thread per target row, 12 register accumulators -> each row loaded ONCE
__global__ void __launch_bounds__(256)
k_head(const int* __restrict__ tgt, const float* __restrict__ Wr,
       const float* __restrict__ br, float* __restrict__ out, int ntgt) {
    __shared__ float Ws[128 * 12];
    for (int i = threadIdx.x; i < 128 * 12; i += 256) Ws[i] = Wr[i];
    __syncthreads();
    int row = blockIdx.x * 256 + threadIdx.x;
    if (row >= ntgt) return;
    const float* __restrict__ h = g_out + (size_t)tgt[row] * 128;
    float acc[12];
#pragma unroll
    for (int c = 0; c < 12; c++) acc[c] = br[c];
#pragma unroll 4
    for (int k = 0; k < 128; k += 4) {
        float4 hv = *reinterpret_cast<const float4*>(h + k);
#pragma unroll
        for (int c = 0; c < 12; c++) {
            acc[c] = fmaf(hv.x, Ws[(k + 0) * 12 + c], acc[c]);
            acc[c] = fmaf(hv.y, Ws[(k + 1) * 12 + c], acc[c]);
            acc[c] = fmaf(hv.z, Ws[(k + 2) * 12 + c], acc[c]);
            acc[c] = fmaf(hv.w, Ws[(k + 3) * 12 + c], acc[c]);
        }
    }
#pragma unroll
    for (int c = 0; c < 12; c++) out[row * 12 + c] = acc[c];
}

// ---------------- launch ----------------
extern "C" void kernel_launch(void* const* d_in, const int* in_sizes, int n_in,
                              void* d_out, int out_size) {
    const float* x  = (const float*)d_in[0];
    const int*   ei = (const int*)d_in[1];
    const int*  tgt = (const int*)d_in[2];
    const float* W1 = (const float*)d_in[3];
    const float* b1 = (const float*)d_in[4];
    const float* W2 = (const float*)d_in[5];
    const float* b2 = (const float*)d_in[6];
    const float* W3 = (const float*)d_in[7];
    const float* b3 = (const float*)d_in[8];
    const float* Wr = (const float*)d_in[9];
    const float* br = (const float*)d_in[10];

    int n    = in_sizes[0] / 128;   // 50000
    int m    = in_sizes[1] / 2;     // 800000
    int ntgt = in_sizes[2];         // 8192

    int sblocks = (n + 255) / 256;  // 196 <= 256
    int gblocks = (n + 63) / 64;
    int ablocks = (n + 7) / 8;

    // gemm1 hoisted to launch index 3 (depends only on dinv from scan1):
    // puts k_gemm in the ncu profiling window next round. CSR finish
    // (scan2/scan3/fill) runs before agg1, which is the first consumer.
    k_init<<<sblocks, 256>>>(n);                       // 0
    k_hist<<<(m + 255) / 256, 256>>>(ei, m);           // 1
    k_scan1<<<sblocks, 256>>>(n);                      // 2 (also dinv)
    k_gemm<<<gblocks, 256>>>(x, W1, n, 0);             // 3 <- profiled
    k_scan2<<<1, 256>>>(sblocks, n);                   // 4
    k_scan3<<<sblocks, 256>>>(n);                      // 5
    k_fill<<<(m + 255) / 256, 256>>>(ei, m);           // 6
    k_agg<<<ablocks, 256>>>(b1, n);                    // 7
    k_gemm<<<gblocks, 256>>>(nullptr, W2, n, 1);
    k_agg<<<ablocks, 256>>>(b2, n);
    k_gemm<<<gblocks, 256>>>(nullptr, W3, n, 1);
    k_agg<<<ablocks, 256>>>(b3, n);

    k_head<<<(ntgt * 12 + 255) / 256, 256>>>(tgt, Wr, br, (float*)d_out, ntgt);
}